// round 5
// baseline (speedup 1.0000x reference)
#include <cuda_runtime.h>
#include <cuda_bf16.h>

#define N_NODES 100000
#define N_EDGES 1600000
#define D 64

// ---------------------------------------------------------------------------
// Scratch (no cudaMalloc allowed): ~33 MB total
// ---------------------------------------------------------------------------
__device__ float g_emb[N_NODES * D];        // elu(x*w), 25.6 MB (L2-resident)
__device__ int   g_counts[N_NODES];         // per-dst degree
__device__ int   g_offsets[N_NODES + 1];    // CSR row offsets (exclusive scan)
__device__ int   g_cursor[N_NODES];         // running insert cursor per dst
__device__ int   g_edge_src[N_EDGES];       // src ids binned by dst, 6.4 MB

// ---------------------------------------------------------------------------
// K1: emb = elu(x * w); also zero the histogram counters.
// One thread per float4 (1.6M threads).
// ---------------------------------------------------------------------------
__global__ void __launch_bounds__(256) prep_kernel(
    const float* __restrict__ x,     // [N, D]
    const float* __restrict__ w)     // [1, D]
{
    int i = blockIdx.x * blockDim.x + threadIdx.x;
    if (i < N_NODES) g_counts[i] = 0;

    const int total = N_NODES * D / 4;
    if (i >= total) return;

    float4 xv = reinterpret_cast<const float4*>(x)[i];
    int c4 = i & 15;
    float4 wv = reinterpret_cast<const float4*>(w)[c4];

    float4 e;
    float p;
    p = xv.x * wv.x; e.x = p > 0.f ? p : (__expf(p) - 1.f);
    p = xv.y * wv.y; e.y = p > 0.f ? p : (__expf(p) - 1.f);
    p = xv.z * wv.z; e.z = p > 0.f ? p : (__expf(p) - 1.f);
    p = xv.w * wv.w; e.w = p > 0.f ? p : (__expf(p) - 1.f);

    reinterpret_cast<float4*>(g_emb)[i] = e;
}

// ---------------------------------------------------------------------------
// K2: histogram of destinations. 1.6M spread atomics (fast REDG path).
// ---------------------------------------------------------------------------
__global__ void __launch_bounds__(256) hist_kernel(const int* __restrict__ dst)
{
    int e = blockIdx.x * blockDim.x + threadIdx.x;
    if (e < N_EDGES) atomicAdd(&g_counts[__ldg(dst + e)], 1);
}

// ---------------------------------------------------------------------------
// K3: exclusive scan of g_counts -> g_offsets (and seed g_cursor).
// Single block, 1024 threads, 4 items/thread => 25 block-strided iterations.
// ---------------------------------------------------------------------------
__global__ void __launch_bounds__(1024) scan_kernel()
{
    __shared__ int warp_sums[32];
    __shared__ int s_running;
    const int tid  = threadIdx.x;
    const int lane = tid & 31;
    const int wid  = tid >> 5;

    if (tid == 0) s_running = 0;
    __syncthreads();

    for (int base = 0; base < N_NODES; base += 1024 * 4) {
        int i = base + tid * 4;
        int4 c = make_int4(0, 0, 0, 0);
        if (i + 3 < N_NODES)
            c = *reinterpret_cast<const int4*>(g_counts + i);

        // serial prefix over the 4 items
        int t0 = c.x;
        int t1 = t0 + c.y;
        int t2 = t1 + c.z;
        int t3 = t2 + c.w;      // thread total

        // inclusive warp scan of thread totals
        int x = t3;
        #pragma unroll
        for (int o = 1; o < 32; o <<= 1) {
            int y = __shfl_up_sync(0xFFFFFFFFu, x, o);
            if (lane >= o) x += y;
        }
        if (lane == 31) warp_sums[wid] = x;
        __syncthreads();
        if (wid == 0) {
            int wv = warp_sums[lane];
            #pragma unroll
            for (int o = 1; o < 32; o <<= 1) {
                int y = __shfl_up_sync(0xFFFFFFFFu, wv, o);
                if (lane >= o) wv += y;
            }
            warp_sums[lane] = wv;   // inclusive over warps
        }
        __syncthreads();

        int warp_excl = (wid == 0) ? 0 : warp_sums[wid - 1];
        int thr_excl  = x - t3 + warp_excl;      // exclusive for this thread
        int run       = s_running;

        if (i + 3 < N_NODES) {
            int4 off = make_int4(run + thr_excl,
                                 run + thr_excl + t0,
                                 run + thr_excl + t1,
                                 run + thr_excl + t2);
            *reinterpret_cast<int4*>(g_offsets + i) = off;
            *reinterpret_cast<int4*>(g_cursor  + i) = off;
        }

        int block_total = warp_sums[31];
        __syncthreads();                 // everyone done reading s_running/warp_sums
        if (tid == 0) s_running = run + block_total;
        __syncthreads();
    }
    if (tid == 0) g_offsets[N_NODES] = s_running;   // == N_EDGES
}

// ---------------------------------------------------------------------------
// K4: permute edges into CSR bins: g_edge_src[bin(dst)] = src.
// ---------------------------------------------------------------------------
__global__ void __launch_bounds__(256) permute_kernel(
    const int* __restrict__ src,
    const int* __restrict__ dst)
{
    int e = blockIdx.x * blockDim.x + threadIdx.x;
    if (e >= N_EDGES) return;
    int d = __ldg(dst + e);
    int pos = atomicAdd(&g_cursor[d], 1);
    g_edge_src[pos] = __ldg(src + e);
}

// ---------------------------------------------------------------------------
// K5: pull-mode gather-sum. 16 threads per node; each thread owns one float4
// of the row, accumulates over the node's incoming edges in registers,
// writes once. Zero atomics. 2-way unrolled edge loop for MLP.
// ---------------------------------------------------------------------------
__global__ void __launch_bounds__(256) gather_kernel(float* __restrict__ out)
{
    int t = blockIdx.x * blockDim.x + threadIdx.x;
    int node = t >> 4;
    int part = t & 15;
    if (node >= N_NODES) return;

    int beg = __ldg(g_offsets + node);
    int end = __ldg(g_offsets + node + 1);

    const float4* emb4 = reinterpret_cast<const float4*>(g_emb);

    float4 a0 = make_float4(0.f, 0.f, 0.f, 0.f);
    float4 a1 = make_float4(0.f, 0.f, 0.f, 0.f);

    int j = beg;
    for (; j + 1 < end; j += 2) {
        int s0 = __ldg(g_edge_src + j);
        int s1 = __ldg(g_edge_src + j + 1);
        float4 v0 = __ldg(emb4 + s0 * 16 + part);
        float4 v1 = __ldg(emb4 + s1 * 16 + part);
        a0.x += v0.x; a0.y += v0.y; a0.z += v0.z; a0.w += v0.w;
        a1.x += v1.x; a1.y += v1.y; a1.z += v1.z; a1.w += v1.w;
    }
    if (j < end) {
        int s0 = __ldg(g_edge_src + j);
        float4 v0 = __ldg(emb4 + s0 * 16 + part);
        a0.x += v0.x; a0.y += v0.y; a0.z += v0.z; a0.w += v0.w;
    }

    float4 r = make_float4(a0.x + a1.x, a0.y + a1.y, a0.z + a1.z, a0.w + a1.w);
    reinterpret_cast<float4*>(out)[node * 16 + part] = r;
}

// ---------------------------------------------------------------------------
extern "C" void kernel_launch(void* const* d_in, const int* in_sizes, int n_in,
                              void* d_out, int out_size)
{
    const float* x   = (const float*)d_in[0];   // [100000, 64]
    const float* w   = (const float*)d_in[1];   // [1, 64]
    const int*   src = (const int*)d_in[2];     // [1600000]
    const int*   dst = (const int*)d_in[3];     // [1600000]
    float* out = (float*)d_out;                 // [100000, 64]

    const int total4 = N_NODES * D / 4;         // 1.6M
    prep_kernel<<<(total4 + 255) / 256, 256>>>(x, w);

    hist_kernel<<<(N_EDGES + 255) / 256, 256>>>(dst);

    scan_kernel<<<1, 1024>>>();

    permute_kernel<<<(N_EDGES + 255) / 256, 256>>>(src, dst);

    const int gt = N_NODES * 16;                // 1.6M threads
    gather_kernel<<<(gt + 255) / 256, 256>>>(out);
}

// round 6
// speedup vs baseline: 1.0180x; 1.0180x over previous
#include <cuda_runtime.h>
#include <cuda_bf16.h>

#define N_NODES 100000
#define N_EDGES 1600000
#define D 64

// ---------------------------------------------------------------------------
// Scratch (no cudaMalloc allowed). __device__ globals are zero-initialized at
// module load; g_counts is re-zeroed by the gather epilogue each call, so
// every invocation of kernel_launch sees counts == 0 (deterministic).
// ---------------------------------------------------------------------------
__device__ float g_emb[N_NODES * D];        // elu(x*w), 25.6 MB (L2-resident)
__device__ int   g_counts[N_NODES];         // per-dst degree (always 0 on entry)
__device__ int   g_offsets[N_NODES + 1];    // CSR row offsets
__device__ int   g_cursor[N_NODES];         // insert cursors
__device__ int   g_edge_src[N_EDGES];       // src ids binned by dst

// ---------------------------------------------------------------------------
// K1: fused  (a) emb = elu(x*w)  [one float4 per thread, 1.6M threads]
//            (b) dst histogram   [4 edges per thread, first 400K threads]
// The two halves are independent; the atomics' latency hides under the
// MUFU/FMA + memory work of (a).
// ---------------------------------------------------------------------------
__global__ void __launch_bounds__(256) prep_hist_kernel(
    const float* __restrict__ x,     // [N, D]
    const float* __restrict__ w,     // [1, D]
    const int*   __restrict__ dst)   // [E]
{
    int i = blockIdx.x * blockDim.x + threadIdx.x;

    // ---- histogram part: 4 edges per thread via int4 ----
    if (i < N_EDGES / 4) {
        int4 d4 = __ldg(reinterpret_cast<const int4*>(dst) + i);
        atomicAdd(&g_counts[d4.x], 1);
        atomicAdd(&g_counts[d4.y], 1);
        atomicAdd(&g_counts[d4.z], 1);
        atomicAdd(&g_counts[d4.w], 1);
    }

    // ---- elu part ----
    const int total = N_NODES * D / 4;          // 1.6M float4s
    if (i >= total) return;

    float4 xv = __ldg(reinterpret_cast<const float4*>(x) + i);
    float4 wv = __ldg(reinterpret_cast<const float4*>(w) + (i & 15));

    float4 e;
    float p;
    p = xv.x * wv.x; e.x = p > 0.f ? p : (__expf(p) - 1.f);
    p = xv.y * wv.y; e.y = p > 0.f ? p : (__expf(p) - 1.f);
    p = xv.z * wv.z; e.z = p > 0.f ? p : (__expf(p) - 1.f);
    p = xv.w * wv.w; e.w = p > 0.f ? p : (__expf(p) - 1.f);

    reinterpret_cast<float4*>(g_emb)[i] = e;
}

// ---------------------------------------------------------------------------
// K2: exclusive scan of g_counts -> g_offsets (+ seed g_cursor).
// Single block, 1024 threads, 4 items/thread, 25 strided iterations.
// ---------------------------------------------------------------------------
__global__ void __launch_bounds__(1024) scan_kernel()
{
    __shared__ int warp_sums[32];
    __shared__ int s_running;
    const int tid  = threadIdx.x;
    const int lane = tid & 31;
    const int wid  = tid >> 5;

    if (tid == 0) s_running = 0;
    __syncthreads();

    for (int base = 0; base < N_NODES; base += 1024 * 4) {
        int i = base + tid * 4;
        int4 c = make_int4(0, 0, 0, 0);
        if (i + 3 < N_NODES)
            c = *reinterpret_cast<const int4*>(g_counts + i);

        int t0 = c.x;
        int t1 = t0 + c.y;
        int t2 = t1 + c.z;
        int t3 = t2 + c.w;

        int xsum = t3;
        #pragma unroll
        for (int o = 1; o < 32; o <<= 1) {
            int y = __shfl_up_sync(0xFFFFFFFFu, xsum, o);
            if (lane >= o) xsum += y;
        }
        if (lane == 31) warp_sums[wid] = xsum;
        __syncthreads();
        if (wid == 0) {
            int wv = warp_sums[lane];
            #pragma unroll
            for (int o = 1; o < 32; o <<= 1) {
                int y = __shfl_up_sync(0xFFFFFFFFu, wv, o);
                if (lane >= o) wv += y;
            }
            warp_sums[lane] = wv;
        }
        __syncthreads();

        int warp_excl = (wid == 0) ? 0 : warp_sums[wid - 1];
        int thr_excl  = xsum - t3 + warp_excl;
        int run       = s_running;

        if (i + 3 < N_NODES) {
            int4 off = make_int4(run + thr_excl,
                                 run + thr_excl + t0,
                                 run + thr_excl + t1,
                                 run + thr_excl + t2);
            *reinterpret_cast<int4*>(g_offsets + i) = off;
            *reinterpret_cast<int4*>(g_cursor  + i) = off;
        }

        int block_total = warp_sums[31];
        __syncthreads();
        if (tid == 0) s_running = run + block_total;
        __syncthreads();
    }
    if (tid == 0) g_offsets[N_NODES] = s_running;   // == N_EDGES
}

// ---------------------------------------------------------------------------
// K3: permute edges into CSR bins, 8 edges per thread for MLP.
// 8 independent atomicAdd chains per thread (was 1 -> issue=4.4%).
// ---------------------------------------------------------------------------
__global__ void __launch_bounds__(256) permute_kernel(
    const int* __restrict__ src,
    const int* __restrict__ dst)
{
    int t = blockIdx.x * blockDim.x + threadIdx.x;
    int e = t * 8;
    if (e >= N_EDGES) return;

    int4 d0 = __ldg(reinterpret_cast<const int4*>(dst + e));
    int4 d1 = __ldg(reinterpret_cast<const int4*>(dst + e) + 1);
    int4 s0 = __ldg(reinterpret_cast<const int4*>(src + e));
    int4 s1 = __ldg(reinterpret_cast<const int4*>(src + e) + 1);

    int p0 = atomicAdd(&g_cursor[d0.x], 1);
    int p1 = atomicAdd(&g_cursor[d0.y], 1);
    int p2 = atomicAdd(&g_cursor[d0.z], 1);
    int p3 = atomicAdd(&g_cursor[d0.w], 1);
    int p4 = atomicAdd(&g_cursor[d1.x], 1);
    int p5 = atomicAdd(&g_cursor[d1.y], 1);
    int p6 = atomicAdd(&g_cursor[d1.z], 1);
    int p7 = atomicAdd(&g_cursor[d1.w], 1);

    g_edge_src[p0] = s0.x;
    g_edge_src[p1] = s0.y;
    g_edge_src[p2] = s0.z;
    g_edge_src[p3] = s0.w;
    g_edge_src[p4] = s1.x;
    g_edge_src[p5] = s1.y;
    g_edge_src[p6] = s1.z;
    g_edge_src[p7] = s1.w;
}

// ---------------------------------------------------------------------------
// K4: pull-mode gather-sum. 16 threads per node; each owns one float4 of the
// row. 4-way unrolled edge loop: 4 independent index loads then 4 independent
// 256B row gathers per iteration (MLP>=4). Zero atomics; one store per part.
// Epilogue re-zeroes g_counts for the next invocation.
// ---------------------------------------------------------------------------
__global__ void __launch_bounds__(256) gather_kernel(float* __restrict__ out)
{
    int t = blockIdx.x * blockDim.x + threadIdx.x;
    int node = t >> 4;
    int part = t & 15;
    if (node >= N_NODES) return;

    int beg = __ldg(g_offsets + node);
    int end = __ldg(g_offsets + node + 1);

    const float4* emb4 = reinterpret_cast<const float4*>(g_emb);

    float4 a0 = make_float4(0.f, 0.f, 0.f, 0.f);
    float4 a1 = make_float4(0.f, 0.f, 0.f, 0.f);

    int j = beg;
    for (; j + 4 <= end; j += 4) {
        int s0 = __ldg(g_edge_src + j);
        int s1 = __ldg(g_edge_src + j + 1);
        int s2 = __ldg(g_edge_src + j + 2);
        int s3 = __ldg(g_edge_src + j + 3);
        float4 v0 = __ldg(emb4 + s0 * 16 + part);
        float4 v1 = __ldg(emb4 + s1 * 16 + part);
        float4 v2 = __ldg(emb4 + s2 * 16 + part);
        float4 v3 = __ldg(emb4 + s3 * 16 + part);
        a0.x += v0.x; a0.y += v0.y; a0.z += v0.z; a0.w += v0.w;
        a1.x += v1.x; a1.y += v1.y; a1.z += v1.z; a1.w += v1.w;
        a0.x += v2.x; a0.y += v2.y; a0.z += v2.z; a0.w += v2.w;
        a1.x += v3.x; a1.y += v3.y; a1.z += v3.z; a1.w += v3.w;
    }
    for (; j < end; j++) {
        int s0 = __ldg(g_edge_src + j);
        float4 v0 = __ldg(emb4 + s0 * 16 + part);
        a0.x += v0.x; a0.y += v0.y; a0.z += v0.z; a0.w += v0.w;
    }

    float4 r = make_float4(a0.x + a1.x, a0.y + a1.y, a0.z + a1.z, a0.w + a1.w);
    reinterpret_cast<float4*>(out)[node * 16 + part] = r;

    if (part == 0) g_counts[node] = 0;   // restore invariant for next call
}

// ---------------------------------------------------------------------------
extern "C" void kernel_launch(void* const* d_in, const int* in_sizes, int n_in,
                              void* d_out, int out_size)
{
    const float* x   = (const float*)d_in[0];   // [100000, 64]
    const float* w   = (const float*)d_in[1];   // [1, 64]
    const int*   src = (const int*)d_in[2];     // [1600000]
    const int*   dst = (const int*)d_in[3];     // [1600000]
    float* out = (float*)d_out;                 // [100000, 64]

    const int total4 = N_NODES * D / 4;         // 1.6M threads
    prep_hist_kernel<<<(total4 + 255) / 256, 256>>>(x, w, dst);

    scan_kernel<<<1, 1024>>>();

    permute_kernel<<<(N_EDGES / 8 + 255) / 256, 256>>>(src, dst);

    const int gt = N_NODES * 16;                // 1.6M threads
    gather_kernel<<<(gt + 255) / 256, 256>>>(out);
}

// round 7
// speedup vs baseline: 1.3137x; 1.2904x over previous
#include <cuda_runtime.h>
#include <cuda_bf16.h>

#define N_NODES 100000
#define N_EDGES 1600000
#define D 64

#define N4 (N_NODES / 4)            // 25000 int4 count words
#define SCAN_BLOCKS ((N4 + 255) / 256)   // 98

// ---------------------------------------------------------------------------
// Scratch (no cudaMalloc allowed). __device__ globals are zero-initialized at
// module load; g_counts is re-zeroed by the gather epilogue each call, so
// every invocation of kernel_launch sees counts == 0 (deterministic).
// ---------------------------------------------------------------------------
__device__ float g_emb[N_NODES * D];        // elu(x*w), 25.6 MB (L2-resident)
__device__ int   g_counts[N_NODES];         // per-dst degree (always 0 on entry)
__device__ int   g_offsets[N_NODES + 1];    // CSR row offsets
__device__ int   g_cursor[N_NODES];         // insert cursors
__device__ int   g_edge_src[N_EDGES];       // src ids binned by dst
__device__ int   g_psum[SCAN_BLOCKS];       // per-block totals
__device__ int   g_pbase[SCAN_BLOCKS];      // per-block exclusive bases

// ---------------------------------------------------------------------------
// K1: fused  (a) emb = elu(x*w)  [one float4 per thread, 1.6M threads]
//            (b) dst histogram   [4 edges per thread, first 400K threads]
// ---------------------------------------------------------------------------
__global__ void __launch_bounds__(256) prep_hist_kernel(
    const float* __restrict__ x,     // [N, D]
    const float* __restrict__ w,     // [1, D]
    const int*   __restrict__ dst)   // [E]
{
    int i = blockIdx.x * blockDim.x + threadIdx.x;

    if (i < N_EDGES / 4) {
        int4 d4 = __ldg(reinterpret_cast<const int4*>(dst) + i);
        atomicAdd(&g_counts[d4.x], 1);
        atomicAdd(&g_counts[d4.y], 1);
        atomicAdd(&g_counts[d4.z], 1);
        atomicAdd(&g_counts[d4.w], 1);
    }

    const int total = N_NODES * D / 4;          // 1.6M float4s
    if (i >= total) return;

    float4 xv = __ldg(reinterpret_cast<const float4*>(x) + i);
    float4 wv = __ldg(reinterpret_cast<const float4*>(w) + (i & 15));

    float4 e;
    float p;
    p = xv.x * wv.x; e.x = p > 0.f ? p : (__expf(p) - 1.f);
    p = xv.y * wv.y; e.y = p > 0.f ? p : (__expf(p) - 1.f);
    p = xv.z * wv.z; e.z = p > 0.f ? p : (__expf(p) - 1.f);
    p = xv.w * wv.w; e.w = p > 0.f ? p : (__expf(p) - 1.f);

    reinterpret_cast<float4*>(g_emb)[i] = e;
}

// ---------------------------------------------------------------------------
// K2a: per-block local scan. Block b handles int4 words [b*256, b*256+256)
// of g_counts (1024 counts). Writes LOCAL exclusive offsets into g_offsets
// and the block total into g_psum[b].
// ---------------------------------------------------------------------------
__global__ void __launch_bounds__(256) scan_part_kernel()
{
    __shared__ int warp_sums[8];
    const int b    = blockIdx.x;
    const int tid  = threadIdx.x;
    const int lane = tid & 31;
    const int wid  = tid >> 5;

    int i4 = b * 256 + tid;
    int4 c = make_int4(0, 0, 0, 0);
    if (i4 < N4) c = reinterpret_cast<const int4*>(g_counts)[i4];

    int t0 = c.x;
    int t1 = t0 + c.y;
    int t2 = t1 + c.z;
    int t3 = t2 + c.w;

    int x = t3;
    #pragma unroll
    for (int o = 1; o < 32; o <<= 1) {
        int y = __shfl_up_sync(0xFFFFFFFFu, x, o);
        if (lane >= o) x += y;
    }
    if (lane == 31) warp_sums[wid] = x;
    __syncthreads();

    int warp_excl = 0;
    #pragma unroll
    for (int wi = 0; wi < 8; wi++)
        if (wi < wid) warp_excl += warp_sums[wi];

    int thr_excl = warp_excl + x - t3;

    if (i4 < N4) {
        int4 off = make_int4(thr_excl, thr_excl + t0, thr_excl + t1, thr_excl + t2);
        reinterpret_cast<int4*>(g_offsets)[i4] = off;
    }

    if (tid == 255) g_psum[b] = warp_excl + x;   // block total
}

// ---------------------------------------------------------------------------
// K2b: scan the 98 block totals -> exclusive bases. One tiny block.
// ---------------------------------------------------------------------------
__global__ void __launch_bounds__(128) scan_root_kernel()
{
    __shared__ int ws[4];
    const int tid  = threadIdx.x;
    const int lane = tid & 31;
    const int wid  = tid >> 5;

    int v = (tid < SCAN_BLOCKS) ? g_psum[tid] : 0;
    int x = v;
    #pragma unroll
    for (int o = 1; o < 32; o <<= 1) {
        int y = __shfl_up_sync(0xFFFFFFFFu, x, o);
        if (lane >= o) x += y;
    }
    if (lane == 31) ws[wid] = x;
    __syncthreads();

    int wexcl = 0;
    #pragma unroll
    for (int wi = 0; wi < 4; wi++)
        if (wi < wid) wexcl += ws[wi];

    if (tid < SCAN_BLOCKS) g_pbase[tid] = wexcl + x - v;
}

// ---------------------------------------------------------------------------
// K2c: add block bases to local offsets; seed cursors; finalize sentinel.
// ---------------------------------------------------------------------------
__global__ void __launch_bounds__(256) scan_add_kernel()
{
    const int b   = blockIdx.x;
    const int tid = threadIdx.x;
    int base = __ldg(g_pbase + b);

    int i4 = b * 256 + tid;
    if (i4 < N4) {
        int4 o = reinterpret_cast<const int4*>(g_offsets)[i4];
        o.x += base; o.y += base; o.z += base; o.w += base;
        reinterpret_cast<int4*>(g_offsets)[i4] = o;
        reinterpret_cast<int4*>(g_cursor)[i4]  = o;
    }
    if (b == 0 && tid == 0) g_offsets[N_NODES] = N_EDGES;
}

// ---------------------------------------------------------------------------
// K3: permute edges into CSR bins, 8 edges per thread for MLP.
// ---------------------------------------------------------------------------
__global__ void __launch_bounds__(256) permute_kernel(
    const int* __restrict__ src,
    const int* __restrict__ dst)
{
    int t = blockIdx.x * blockDim.x + threadIdx.x;
    int e = t * 8;
    if (e >= N_EDGES) return;

    int4 d0 = __ldg(reinterpret_cast<const int4*>(dst + e));
    int4 d1 = __ldg(reinterpret_cast<const int4*>(dst + e) + 1);
    int4 s0 = __ldg(reinterpret_cast<const int4*>(src + e));
    int4 s1 = __ldg(reinterpret_cast<const int4*>(src + e) + 1);

    int p0 = atomicAdd(&g_cursor[d0.x], 1);
    int p1 = atomicAdd(&g_cursor[d0.y], 1);
    int p2 = atomicAdd(&g_cursor[d0.z], 1);
    int p3 = atomicAdd(&g_cursor[d0.w], 1);
    int p4 = atomicAdd(&g_cursor[d1.x], 1);
    int p5 = atomicAdd(&g_cursor[d1.y], 1);
    int p6 = atomicAdd(&g_cursor[d1.z], 1);
    int p7 = atomicAdd(&g_cursor[d1.w], 1);

    g_edge_src[p0] = s0.x;
    g_edge_src[p1] = s0.y;
    g_edge_src[p2] = s0.z;
    g_edge_src[p3] = s0.w;
    g_edge_src[p4] = s1.x;
    g_edge_src[p5] = s1.y;
    g_edge_src[p6] = s1.z;
    g_edge_src[p7] = s1.w;
}

// ---------------------------------------------------------------------------
// K4: pull-mode gather-sum. 16 threads per node; each owns one float4 of the
// row. 4-way unrolled edge loop. Zero atomics; one store per part.
// Epilogue re-zeroes g_counts for the next invocation.
// ---------------------------------------------------------------------------
__global__ void __launch_bounds__(256) gather_kernel(float* __restrict__ out)
{
    int t = blockIdx.x * blockDim.x + threadIdx.x;
    int node = t >> 4;
    int part = t & 15;
    if (node >= N_NODES) return;

    int beg = __ldg(g_offsets + node);
    int end = __ldg(g_offsets + node + 1);

    const float4* emb4 = reinterpret_cast<const float4*>(g_emb);

    float4 a0 = make_float4(0.f, 0.f, 0.f, 0.f);
    float4 a1 = make_float4(0.f, 0.f, 0.f, 0.f);

    int j = beg;
    for (; j + 4 <= end; j += 4) {
        int s0 = __ldg(g_edge_src + j);
        int s1 = __ldg(g_edge_src + j + 1);
        int s2 = __ldg(g_edge_src + j + 2);
        int s3 = __ldg(g_edge_src + j + 3);
        float4 v0 = __ldg(emb4 + s0 * 16 + part);
        float4 v1 = __ldg(emb4 + s1 * 16 + part);
        float4 v2 = __ldg(emb4 + s2 * 16 + part);
        float4 v3 = __ldg(emb4 + s3 * 16 + part);
        a0.x += v0.x; a0.y += v0.y; a0.z += v0.z; a0.w += v0.w;
        a1.x += v1.x; a1.y += v1.y; a1.z += v1.z; a1.w += v1.w;
        a0.x += v2.x; a0.y += v2.y; a0.z += v2.z; a0.w += v2.w;
        a1.x += v3.x; a1.y += v3.y; a1.z += v3.z; a1.w += v3.w;
    }
    for (; j < end; j++) {
        int s0 = __ldg(g_edge_src + j);
        float4 v0 = __ldg(emb4 + s0 * 16 + part);
        a0.x += v0.x; a0.y += v0.y; a0.z += v0.z; a0.w += v0.w;
    }

    float4 r = make_float4(a0.x + a1.x, a0.y + a1.y, a0.z + a1.z, a0.w + a1.w);
    reinterpret_cast<float4*>(out)[node * 16 + part] = r;

    if (part == 0) g_counts[node] = 0;   // restore invariant for next call
}

// ---------------------------------------------------------------------------
extern "C" void kernel_launch(void* const* d_in, const int* in_sizes, int n_in,
                              void* d_out, int out_size)
{
    const float* x   = (const float*)d_in[0];   // [100000, 64]
    const float* w   = (const float*)d_in[1];   // [1, 64]
    const int*   src = (const int*)d_in[2];     // [1600000]
    const int*   dst = (const int*)d_in[3];     // [1600000]
    float* out = (float*)d_out;                 // [100000, 64]

    const int total4 = N_NODES * D / 4;         // 1.6M threads
    prep_hist_kernel<<<(total4 + 255) / 256, 256>>>(x, w, dst);

    scan_part_kernel<<<SCAN_BLOCKS, 256>>>();
    scan_root_kernel<<<1, 128>>>();
    scan_add_kernel<<<SCAN_BLOCKS, 256>>>();

    permute_kernel<<<(N_EDGES / 8 + 255) / 256, 256>>>(src, dst);

    const int gt = N_NODES * 16;                // 1.6M threads
    gather_kernel<<<(gt + 255) / 256, 256>>>(out);
}

// round 9
// speedup vs baseline: 1.3862x; 1.0552x over previous
#include <cuda_runtime.h>
#include <cuda_bf16.h>

#define N_NODES 100000
#define N_EDGES 1600000
#define D 64

#define N4 (N_NODES / 4)                  // 25000 int4 count words
#define SCAN_BLOCKS ((N4 + 255) / 256)    // 98 (co-resident on 148 SMs)

// ---------------------------------------------------------------------------
// Scratch (no cudaMalloc allowed). __device__ globals zero-init at load;
// g_counts is re-zeroed by gather's epilogue, g_status by prep_hist, so each
// invocation sees a clean state (deterministic).
// ---------------------------------------------------------------------------
__device__ float g_emb[N_NODES * D];               // elu(x*w), 25.6 MB
__device__ int   g_counts[N_NODES];                // per-dst degree (0 on entry)
__device__ int   g_offsets[N_NODES + 1];           // CSR row offsets
__device__ int   g_cursor[N_NODES];                // insert cursors
__device__ int   g_edge_src[N_EDGES];              // src ids binned by dst
__device__ unsigned long long g_status[SCAN_BLOCKS]; // lookback: (state<<32)|value

// ---------------------------------------------------------------------------
// K1: fused  (a) emb = elu(x*w)       [one float4 per thread, 1.6M threads]
//            (b) dst histogram        [4 edges per thread, first 400K threads]
//            (c) zero lookback flags  [first 98 threads]
// ---------------------------------------------------------------------------
__global__ void __launch_bounds__(256) prep_hist_kernel(
    const float* __restrict__ x,     // [N, D]
    const float* __restrict__ w,     // [1, D]
    const int*   __restrict__ dst)   // [E]
{
    int i = blockIdx.x * blockDim.x + threadIdx.x;

    if (i < SCAN_BLOCKS) g_status[i] = 0ULL;

    if (i < N_EDGES / 4) {
        int4 d4 = __ldg(reinterpret_cast<const int4*>(dst) + i);
        atomicAdd(&g_counts[d4.x], 1);
        atomicAdd(&g_counts[d4.y], 1);
        atomicAdd(&g_counts[d4.z], 1);
        atomicAdd(&g_counts[d4.w], 1);
    }

    const int total = N_NODES * D / 4;          // 1.6M float4s
    if (i >= total) return;

    float4 xv = __ldg(reinterpret_cast<const float4*>(x) + i);
    float4 wv = __ldg(reinterpret_cast<const float4*>(w) + (i & 15));

    float4 e;
    float p;
    p = xv.x * wv.x; e.x = p > 0.f ? p : (__expf(p) - 1.f);
    p = xv.y * wv.y; e.y = p > 0.f ? p : (__expf(p) - 1.f);
    p = xv.z * wv.z; e.z = p > 0.f ? p : (__expf(p) - 1.f);
    p = xv.w * wv.w; e.w = p > 0.f ? p : (__expf(p) - 1.f);

    reinterpret_cast<float4*>(g_emb)[i] = e;
}

// ---------------------------------------------------------------------------
// K2: single-pass decoupled-lookback exclusive scan of g_counts.
// 98 co-resident blocks (< 148 SMs) so spin-waiting cannot deadlock.
// States: 0 = empty, 1 = aggregate ready, 2 = inclusive prefix ready.
// FIX vs R7: block_agg is the sum of ALL 8 warp_sums (was warp_sums[7],
// i.e. only warp 7's total — that corrupted every published prefix).
// ---------------------------------------------------------------------------
__global__ void __launch_bounds__(256) scan_lookback_kernel()
{
    __shared__ int warp_sums[8];
    __shared__ int s_base;
    const int b    = blockIdx.x;
    const int tid  = threadIdx.x;
    const int lane = tid & 31;
    const int wid  = tid >> 5;

    // ---- local scan of this block's 1024 counts ----
    int i4 = b * 256 + tid;
    int4 c = make_int4(0, 0, 0, 0);
    if (i4 < N4) c = reinterpret_cast<const int4*>(g_counts)[i4];

    int t0 = c.x;
    int t1 = t0 + c.y;
    int t2 = t1 + c.z;
    int t3 = t2 + c.w;

    int x = t3;
    #pragma unroll
    for (int o = 1; o < 32; o <<= 1) {
        int y = __shfl_up_sync(0xFFFFFFFFu, x, o);
        if (lane >= o) x += y;
    }
    if (lane == 31) warp_sums[wid] = x;
    __syncthreads();

    int warp_excl = 0;
    int block_agg = 0;
    #pragma unroll
    for (int wi = 0; wi < 8; wi++) {
        int ws = warp_sums[wi];
        if (wi < wid) warp_excl += ws;
        block_agg += ws;                 // full block total (all 8 warps)
    }

    int thr_excl = warp_excl + x - t3;   // local exclusive prefix

    // ---- publish aggregate (block 0 publishes inclusive directly) ----
    if (tid == 0) {
        unsigned long long st = (b == 0)
            ? ((2ULL << 32) | (unsigned)block_agg)
            : ((1ULL << 32) | (unsigned)block_agg);
        atomicExch(&g_status[b], st);
    }

    // ---- warp 0: lookback over predecessors, 32 at a time ----
    if (wid == 0) {
        int base = 0;
        int idx  = b - 1;
        while (idx >= 0) {
            int my = idx - lane;                 // lane 0 reads nearest pred
            unsigned long long s = 0;
            if (my >= 0) {
                do { s = atomicAdd(&g_status[my], 0ULL); } while ((s >> 32) == 0);
            }
            int st  = (my >= 0) ? (int)(s >> 32) : 1;
            int val = (my >= 0) ? (int)(s & 0xFFFFFFFFu) : 0;

            unsigned incl_mask = __ballot_sync(0xFFFFFFFFu, st == 2);
            int contrib;
            if (incl_mask) {
                int fl = __ffs(incl_mask) - 1;   // nearest block w/ inclusive
                contrib = (lane <= fl) ? val : 0;
                #pragma unroll
                for (int o = 16; o; o >>= 1)
                    contrib += __shfl_down_sync(0xFFFFFFFFu, contrib, o);
                base += __shfl_sync(0xFFFFFFFFu, contrib, 0);
                break;
            } else {
                contrib = val;
                #pragma unroll
                for (int o = 16; o; o >>= 1)
                    contrib += __shfl_down_sync(0xFFFFFFFFu, contrib, o);
                base += __shfl_sync(0xFFFFFFFFu, contrib, 0);
                idx -= 32;
            }
        }
        if (lane == 0) {
            s_base = base;
            if (b > 0)   // promote to inclusive for successors
                atomicExch(&g_status[b], (2ULL << 32) | (unsigned)(base + block_agg));
        }
    }
    __syncthreads();

    int base = s_base;
    if (i4 < N4) {
        int e0 = base + thr_excl;
        int4 off = make_int4(e0, e0 + t0, e0 + t1, e0 + t2);
        reinterpret_cast<int4*>(g_offsets)[i4] = off;
        reinterpret_cast<int4*>(g_cursor)[i4]  = off;
    }
    if (b == 0 && tid == 0) g_offsets[N_NODES] = N_EDGES;
}

// ---------------------------------------------------------------------------
// K3: permute edges into CSR bins, 8 edges per thread for MLP.
// ---------------------------------------------------------------------------
__global__ void __launch_bounds__(256) permute_kernel(
    const int* __restrict__ src,
    const int* __restrict__ dst)
{
    int t = blockIdx.x * blockDim.x + threadIdx.x;
    int e = t * 8;
    if (e >= N_EDGES) return;

    int4 d0 = __ldg(reinterpret_cast<const int4*>(dst + e));
    int4 d1 = __ldg(reinterpret_cast<const int4*>(dst + e) + 1);
    int4 s0 = __ldg(reinterpret_cast<const int4*>(src + e));
    int4 s1 = __ldg(reinterpret_cast<const int4*>(src + e) + 1);

    int p0 = atomicAdd(&g_cursor[d0.x], 1);
    int p1 = atomicAdd(&g_cursor[d0.y], 1);
    int p2 = atomicAdd(&g_cursor[d0.z], 1);
    int p3 = atomicAdd(&g_cursor[d0.w], 1);
    int p4 = atomicAdd(&g_cursor[d1.x], 1);
    int p5 = atomicAdd(&g_cursor[d1.y], 1);
    int p6 = atomicAdd(&g_cursor[d1.z], 1);
    int p7 = atomicAdd(&g_cursor[d1.w], 1);

    g_edge_src[p0] = s0.x;
    g_edge_src[p1] = s0.y;
    g_edge_src[p2] = s0.z;
    g_edge_src[p3] = s0.w;
    g_edge_src[p4] = s1.x;
    g_edge_src[p5] = s1.y;
    g_edge_src[p6] = s1.z;
    g_edge_src[p7] = s1.w;
}

// ---------------------------------------------------------------------------
// K4: pull-mode gather-sum. 16 threads per node; each owns one float4 of the
// row. 4-way unrolled edge loop. Zero atomics; one store per part.
// Epilogue re-zeroes g_counts for the next invocation.
// ---------------------------------------------------------------------------
__global__ void __launch_bounds__(256) gather_kernel(float* __restrict__ out)
{
    int t = blockIdx.x * blockDim.x + threadIdx.x;
    int node = t >> 4;
    int part = t & 15;
    if (node >= N_NODES) return;

    int beg = __ldg(g_offsets + node);
    int end = __ldg(g_offsets + node + 1);

    const float4* emb4 = reinterpret_cast<const float4*>(g_emb);

    float4 a0 = make_float4(0.f, 0.f, 0.f, 0.f);
    float4 a1 = make_float4(0.f, 0.f, 0.f, 0.f);

    int j = beg;
    for (; j + 4 <= end; j += 4) {
        int s0 = __ldg(g_edge_src + j);
        int s1 = __ldg(g_edge_src + j + 1);
        int s2 = __ldg(g_edge_src + j + 2);
        int s3 = __ldg(g_edge_src + j + 3);
        float4 v0 = __ldg(emb4 + s0 * 16 + part);
        float4 v1 = __ldg(emb4 + s1 * 16 + part);
        float4 v2 = __ldg(emb4 + s2 * 16 + part);
        float4 v3 = __ldg(emb4 + s3 * 16 + part);
        a0.x += v0.x; a0.y += v0.y; a0.z += v0.z; a0.w += v0.w;
        a1.x += v1.x; a1.y += v1.y; a1.z += v1.z; a1.w += v1.w;
        a0.x += v2.x; a0.y += v2.y; a0.z += v2.z; a0.w += v2.w;
        a1.x += v3.x; a1.y += v3.y; a1.z += v3.z; a1.w += v3.w;
    }
    for (; j < end; j++) {
        int s0 = __ldg(g_edge_src + j);
        float4 v0 = __ldg(emb4 + s0 * 16 + part);
        a0.x += v0.x; a0.y += v0.y; a0.z += v0.z; a0.w += v0.w;
    }

    float4 r = make_float4(a0.x + a1.x, a0.y + a1.y, a0.z + a1.z, a0.w + a1.w);
    reinterpret_cast<float4*>(out)[node * 16 + part] = r;

    if (part == 0) g_counts[node] = 0;   // restore invariant for next call
}

// ---------------------------------------------------------------------------
extern "C" void kernel_launch(void* const* d_in, const int* in_sizes, int n_in,
                              void* d_out, int out_size)
{
    const float* x   = (const float*)d_in[0];   // [100000, 64]
    const float* w   = (const float*)d_in[1];   // [1, 64]
    const int*   src = (const int*)d_in[2];     // [1600000]
    const int*   dst = (const int*)d_in[3];     // [1600000]
    float* out = (float*)d_out;                 // [100000, 64]

    const int total4 = N_NODES * D / 4;         // 1.6M threads
    prep_hist_kernel<<<(total4 + 255) / 256, 256>>>(x, w, dst);

    scan_lookback_kernel<<<SCAN_BLOCKS, 256>>>();

    permute_kernel<<<(N_EDGES / 8 + 255) / 256, 256>>>(src, dst);

    const int gt = N_NODES * 16;                // 1.6M threads
    gather_kernel<<<(gt + 255) / 256, 256>>>(out);
}

// round 10
// speedup vs baseline: 1.5726x; 1.1345x over previous
#include <cuda_runtime.h>
#include <cuda_bf16.h>
#include <cuda_fp16.h>

#define N_NODES 100000
#define N_EDGES 1600000
#define D 64

#define N4 (N_NODES / 4)                  // 25000 int4 count words
#define SCAN_BLOCKS ((N4 + 255) / 256)    // 98 (co-resident on 148 SMs)

// ---------------------------------------------------------------------------
// Scratch (no cudaMalloc allowed). __device__ globals zero-init at load;
// g_counts re-zeroed by gather's epilogue, g_status by prep_hist, so each
// invocation sees a clean state (deterministic).
// ---------------------------------------------------------------------------
__device__ __half g_emb_h[N_NODES * D];            // elu(x*w) in fp16, 12.8 MB
__device__ int    g_counts[N_NODES];               // per-dst degree (0 on entry)
__device__ int    g_offsets[N_NODES + 1];          // CSR row offsets
__device__ int    g_cursor[N_NODES];               // insert cursors
__device__ int    g_edge_src[N_EDGES];             // src ids binned by dst
__device__ unsigned long long g_status[SCAN_BLOCKS]; // lookback: (state<<32)|value

// ---------------------------------------------------------------------------
// K1: fused  (a) emb = elu(x*w) -> fp16   [one float4 per thread, 1.6M thr]
//            (b) dst histogram            [4 edges per thread, first 400K thr]
//            (c) zero lookback flags      [first 98 threads]
// ---------------------------------------------------------------------------
__global__ void __launch_bounds__(256) prep_hist_kernel(
    const float* __restrict__ x,     // [N, D]
    const float* __restrict__ w,     // [1, D]
    const int*   __restrict__ dst)   // [E]
{
    int i = blockIdx.x * blockDim.x + threadIdx.x;

    if (i < SCAN_BLOCKS) g_status[i] = 0ULL;

    if (i < N_EDGES / 4) {
        int4 d4 = __ldg(reinterpret_cast<const int4*>(dst) + i);
        atomicAdd(&g_counts[d4.x], 1);
        atomicAdd(&g_counts[d4.y], 1);
        atomicAdd(&g_counts[d4.z], 1);
        atomicAdd(&g_counts[d4.w], 1);
    }

    const int total = N_NODES * D / 4;          // 1.6M float4s
    if (i >= total) return;

    float4 xv = __ldg(reinterpret_cast<const float4*>(x) + i);
    float4 wv = __ldg(reinterpret_cast<const float4*>(w) + (i & 15));

    float4 e;
    float p;
    p = xv.x * wv.x; e.x = p > 0.f ? p : (__expf(p) - 1.f);
    p = xv.y * wv.y; e.y = p > 0.f ? p : (__expf(p) - 1.f);
    p = xv.z * wv.z; e.z = p > 0.f ? p : (__expf(p) - 1.f);
    p = xv.w * wv.w; e.w = p > 0.f ? p : (__expf(p) - 1.f);

    __half2 h01 = __floats2half2_rn(e.x, e.y);
    __half2 h23 = __floats2half2_rn(e.z, e.w);
    uint2 st;
    st.x = *reinterpret_cast<unsigned*>(&h01);
    st.y = *reinterpret_cast<unsigned*>(&h23);
    reinterpret_cast<uint2*>(g_emb_h)[i] = st;   // 4 halfs, 8 bytes
}

// ---------------------------------------------------------------------------
// K2: single-pass decoupled-lookback exclusive scan of g_counts.
// 98 co-resident blocks; states: 0 empty, 1 aggregate, 2 inclusive.
// ---------------------------------------------------------------------------
__global__ void __launch_bounds__(256) scan_lookback_kernel()
{
    __shared__ int warp_sums[8];
    __shared__ int s_base;
    const int b    = blockIdx.x;
    const int tid  = threadIdx.x;
    const int lane = tid & 31;
    const int wid  = tid >> 5;

    int i4 = b * 256 + tid;
    int4 c = make_int4(0, 0, 0, 0);
    if (i4 < N4) c = reinterpret_cast<const int4*>(g_counts)[i4];

    int t0 = c.x;
    int t1 = t0 + c.y;
    int t2 = t1 + c.z;
    int t3 = t2 + c.w;

    int x = t3;
    #pragma unroll
    for (int o = 1; o < 32; o <<= 1) {
        int y = __shfl_up_sync(0xFFFFFFFFu, x, o);
        if (lane >= o) x += y;
    }
    if (lane == 31) warp_sums[wid] = x;
    __syncthreads();

    int warp_excl = 0;
    int block_agg = 0;
    #pragma unroll
    for (int wi = 0; wi < 8; wi++) {
        int ws = warp_sums[wi];
        if (wi < wid) warp_excl += ws;
        block_agg += ws;                 // full block total
    }

    int thr_excl = warp_excl + x - t3;

    if (tid == 0) {
        unsigned long long st = (b == 0)
            ? ((2ULL << 32) | (unsigned)block_agg)
            : ((1ULL << 32) | (unsigned)block_agg);
        atomicExch(&g_status[b], st);
    }

    if (wid == 0) {
        int base = 0;
        int idx  = b - 1;
        while (idx >= 0) {
            int my = idx - lane;
            unsigned long long s = 0;
            if (my >= 0) {
                do { s = atomicAdd(&g_status[my], 0ULL); } while ((s >> 32) == 0);
            }
            int st  = (my >= 0) ? (int)(s >> 32) : 1;
            int val = (my >= 0) ? (int)(s & 0xFFFFFFFFu) : 0;

            unsigned incl_mask = __ballot_sync(0xFFFFFFFFu, st == 2);
            int contrib;
            if (incl_mask) {
                int fl = __ffs(incl_mask) - 1;
                contrib = (lane <= fl) ? val : 0;
                #pragma unroll
                for (int o = 16; o; o >>= 1)
                    contrib += __shfl_down_sync(0xFFFFFFFFu, contrib, o);
                base += __shfl_sync(0xFFFFFFFFu, contrib, 0);
                break;
            } else {
                contrib = val;
                #pragma unroll
                for (int o = 16; o; o >>= 1)
                    contrib += __shfl_down_sync(0xFFFFFFFFu, contrib, o);
                base += __shfl_sync(0xFFFFFFFFu, contrib, 0);
                idx -= 32;
            }
        }
        if (lane == 0) {
            s_base = base;
            if (b > 0)
                atomicExch(&g_status[b], (2ULL << 32) | (unsigned)(base + block_agg));
        }
    }
    __syncthreads();

    int base = s_base;
    if (i4 < N4) {
        int e0 = base + thr_excl;
        int4 off = make_int4(e0, e0 + t0, e0 + t1, e0 + t2);
        reinterpret_cast<int4*>(g_offsets)[i4] = off;
        reinterpret_cast<int4*>(g_cursor)[i4]  = off;
    }
    if (b == 0 && tid == 0) g_offsets[N_NODES] = N_EDGES;
}

// ---------------------------------------------------------------------------
// K3: permute edges into CSR bins, 8 edges per thread for MLP.
// ---------------------------------------------------------------------------
__global__ void __launch_bounds__(256) permute_kernel(
    const int* __restrict__ src,
    const int* __restrict__ dst)
{
    int t = blockIdx.x * blockDim.x + threadIdx.x;
    int e = t * 8;
    if (e >= N_EDGES) return;

    int4 d0 = __ldg(reinterpret_cast<const int4*>(dst + e));
    int4 d1 = __ldg(reinterpret_cast<const int4*>(dst + e) + 1);
    int4 s0 = __ldg(reinterpret_cast<const int4*>(src + e));
    int4 s1 = __ldg(reinterpret_cast<const int4*>(src + e) + 1);

    int p0 = atomicAdd(&g_cursor[d0.x], 1);
    int p1 = atomicAdd(&g_cursor[d0.y], 1);
    int p2 = atomicAdd(&g_cursor[d0.z], 1);
    int p3 = atomicAdd(&g_cursor[d0.w], 1);
    int p4 = atomicAdd(&g_cursor[d1.x], 1);
    int p5 = atomicAdd(&g_cursor[d1.y], 1);
    int p6 = atomicAdd(&g_cursor[d1.z], 1);
    int p7 = atomicAdd(&g_cursor[d1.w], 1);

    g_edge_src[p0] = s0.x;
    g_edge_src[p1] = s0.y;
    g_edge_src[p2] = s0.z;
    g_edge_src[p3] = s0.w;
    g_edge_src[p4] = s1.x;
    g_edge_src[p5] = s1.y;
    g_edge_src[p6] = s1.z;
    g_edge_src[p7] = s1.w;
}

// ---------------------------------------------------------------------------
// K4: pull-mode gather-sum over fp16 messages, fp32 accumulation.
// 8 threads per node; each owns 8 halfs (16 B) of the row. 4-way unrolled.
// Zero atomics; two float4 stores per thread. Epilogue re-zeroes g_counts.
// ---------------------------------------------------------------------------
__device__ __forceinline__ void acc_row(float2 a[4], uint4 v)
{
    float2 f;
    f = __half22float2(*reinterpret_cast<__half2*>(&v.x)); a[0].x += f.x; a[0].y += f.y;
    f = __half22float2(*reinterpret_cast<__half2*>(&v.y)); a[1].x += f.x; a[1].y += f.y;
    f = __half22float2(*reinterpret_cast<__half2*>(&v.z)); a[2].x += f.x; a[2].y += f.y;
    f = __half22float2(*reinterpret_cast<__half2*>(&v.w)); a[3].x += f.x; a[3].y += f.y;
}

__global__ void __launch_bounds__(256) gather_kernel(float* __restrict__ out)
{
    int t = blockIdx.x * blockDim.x + threadIdx.x;
    int node = t >> 3;              // 8 threads per node
    int part = t & 7;               // which 8-half chunk of the 64-wide row
    if (node >= N_NODES) return;

    int beg = __ldg(g_offsets + node);
    int end = __ldg(g_offsets + node + 1);

    const uint4* emb16 = reinterpret_cast<const uint4*>(g_emb_h);  // 8 halfs per uint4

    float2 a[4];
    #pragma unroll
    for (int k = 0; k < 4; k++) a[k] = make_float2(0.f, 0.f);

    int j = beg;
    for (; j + 4 <= end; j += 4) {
        int s0 = __ldg(g_edge_src + j);
        int s1 = __ldg(g_edge_src + j + 1);
        int s2 = __ldg(g_edge_src + j + 2);
        int s3 = __ldg(g_edge_src + j + 3);
        uint4 v0 = __ldg(emb16 + s0 * 8 + part);
        uint4 v1 = __ldg(emb16 + s1 * 8 + part);
        uint4 v2 = __ldg(emb16 + s2 * 8 + part);
        uint4 v3 = __ldg(emb16 + s3 * 8 + part);
        acc_row(a, v0);
        acc_row(a, v1);
        acc_row(a, v2);
        acc_row(a, v3);
    }
    for (; j < end; j++) {
        int s0 = __ldg(g_edge_src + j);
        uint4 v0 = __ldg(emb16 + s0 * 8 + part);
        acc_row(a, v0);
    }

    float4* out4 = reinterpret_cast<float4*>(out);
    out4[node * 16 + part * 2 + 0] = make_float4(a[0].x, a[0].y, a[1].x, a[1].y);
    out4[node * 16 + part * 2 + 1] = make_float4(a[2].x, a[2].y, a[3].x, a[3].y);

    if (part == 0) g_counts[node] = 0;   // restore invariant for next call
}

// ---------------------------------------------------------------------------
extern "C" void kernel_launch(void* const* d_in, const int* in_sizes, int n_in,
                              void* d_out, int out_size)
{
    const float* x   = (const float*)d_in[0];   // [100000, 64]
    const float* w   = (const float*)d_in[1];   // [1, 64]
    const int*   src = (const int*)d_in[2];     // [1600000]
    const int*   dst = (const int*)d_in[3];     // [1600000]
    float* out = (float*)d_out;                 // [100000, 64]

    const int total4 = N_NODES * D / 4;         // 1.6M threads
    prep_hist_kernel<<<(total4 + 255) / 256, 256>>>(x, w, dst);

    scan_lookback_kernel<<<SCAN_BLOCKS, 256>>>();

    permute_kernel<<<(N_EDGES / 8 + 255) / 256, 256>>>(src, dst);

    const int gt = N_NODES * 8;                 // 800K threads
    gather_kernel<<<(gt + 255) / 256, 256>>>(out);
}

// round 11
// speedup vs baseline: 1.6400x; 1.0428x over previous
#include <cuda_runtime.h>
#include <cuda_bf16.h>
#include <cuda_fp16.h>

#define N_NODES 100000
#define N_EDGES 1600000
#define D 64

#define N4 (N_NODES / 4)                  // 25000 int4 count words
#define SCAN_BLOCKS ((N4 + 255) / 256)    // 98 (co-resident on 148 SMs)

// ---------------------------------------------------------------------------
// Scratch (no cudaMalloc allowed). __device__ globals zero-init at load;
// g_counts re-zeroed by gather's epilogue, g_status by hist_kernel, so each
// invocation sees a clean state (deterministic).
// ---------------------------------------------------------------------------
__device__ __half g_emb_h[N_NODES * D];            // elu(x*w) in fp16, 12.8 MB
__device__ int    g_counts[N_NODES];               // per-dst degree (0 on entry)
__device__ int    g_offsets[N_NODES + 1];          // CSR row offsets
__device__ int    g_cursor[N_NODES];               // insert cursors
__device__ int    g_edge_src[N_EDGES];             // src ids binned by dst
__device__ unsigned long long g_status[SCAN_BLOCKS]; // lookback: (state<<32)|value

// ---------------------------------------------------------------------------
// K1: dst histogram ONLY (+ zero lookback flags). The elu is deliberately NOT
// here: nothing in the CSR chain needs it, so it moves off the critical path
// into K3. 4 edges per thread via int4; 400K threads.
// ---------------------------------------------------------------------------
__global__ void __launch_bounds__(256) hist_kernel(const int* __restrict__ dst)
{
    int i = blockIdx.x * blockDim.x + threadIdx.x;

    if (i < SCAN_BLOCKS) g_status[i] = 0ULL;

    if (i < N_EDGES / 4) {
        int4 d4 = __ldg(reinterpret_cast<const int4*>(dst) + i);
        atomicAdd(&g_counts[d4.x], 1);
        atomicAdd(&g_counts[d4.y], 1);
        atomicAdd(&g_counts[d4.z], 1);
        atomicAdd(&g_counts[d4.w], 1);
    }
}

// ---------------------------------------------------------------------------
// K2: single-pass decoupled-lookback exclusive scan of g_counts.
// 98 co-resident blocks; states: 0 empty, 1 aggregate, 2 inclusive.
// ---------------------------------------------------------------------------
__global__ void __launch_bounds__(256) scan_lookback_kernel()
{
    __shared__ int warp_sums[8];
    __shared__ int s_base;
    const int b    = blockIdx.x;
    const int tid  = threadIdx.x;
    const int lane = tid & 31;
    const int wid  = tid >> 5;

    int i4 = b * 256 + tid;
    int4 c = make_int4(0, 0, 0, 0);
    if (i4 < N4) c = reinterpret_cast<const int4*>(g_counts)[i4];

    int t0 = c.x;
    int t1 = t0 + c.y;
    int t2 = t1 + c.z;
    int t3 = t2 + c.w;

    int x = t3;
    #pragma unroll
    for (int o = 1; o < 32; o <<= 1) {
        int y = __shfl_up_sync(0xFFFFFFFFu, x, o);
        if (lane >= o) x += y;
    }
    if (lane == 31) warp_sums[wid] = x;
    __syncthreads();

    int warp_excl = 0;
    int block_agg = 0;
    #pragma unroll
    for (int wi = 0; wi < 8; wi++) {
        int ws = warp_sums[wi];
        if (wi < wid) warp_excl += ws;
        block_agg += ws;                 // full block total (all 8 warps)
    }

    int thr_excl = warp_excl + x - t3;

    if (tid == 0) {
        unsigned long long st = (b == 0)
            ? ((2ULL << 32) | (unsigned)block_agg)
            : ((1ULL << 32) | (unsigned)block_agg);
        atomicExch(&g_status[b], st);
    }

    if (wid == 0) {
        int base = 0;
        int idx  = b - 1;
        while (idx >= 0) {
            int my = idx - lane;
            unsigned long long s = 0;
            if (my >= 0) {
                do { s = atomicAdd(&g_status[my], 0ULL); } while ((s >> 32) == 0);
            }
            int st  = (my >= 0) ? (int)(s >> 32) : 1;
            int val = (my >= 0) ? (int)(s & 0xFFFFFFFFu) : 0;

            unsigned incl_mask = __ballot_sync(0xFFFFFFFFu, st == 2);
            int contrib;
            if (incl_mask) {
                int fl = __ffs(incl_mask) - 1;
                contrib = (lane <= fl) ? val : 0;
                #pragma unroll
                for (int o = 16; o; o >>= 1)
                    contrib += __shfl_down_sync(0xFFFFFFFFu, contrib, o);
                base += __shfl_sync(0xFFFFFFFFu, contrib, 0);
                break;
            } else {
                contrib = val;
                #pragma unroll
                for (int o = 16; o; o >>= 1)
                    contrib += __shfl_down_sync(0xFFFFFFFFu, contrib, o);
                base += __shfl_sync(0xFFFFFFFFu, contrib, 0);
                idx -= 32;
            }
        }
        if (lane == 0) {
            s_base = base;
            if (b > 0)
                atomicExch(&g_status[b], (2ULL << 32) | (unsigned)(base + block_agg));
        }
    }
    __syncthreads();

    int base = s_base;
    if (i4 < N4) {
        int e0 = base + thr_excl;
        int4 off = make_int4(e0, e0 + t0, e0 + t1, e0 + t2);
        reinterpret_cast<int4*>(g_offsets)[i4] = off;
        reinterpret_cast<int4*>(g_cursor)[i4]  = off;
    }
    if (b == 0 && tid == 0) g_offsets[N_NODES] = N_EDGES;
}

// ---------------------------------------------------------------------------
// K3: FUSED permute + elu. The permute half (first 200K threads, 8 edges
// each) is atomic-latency bound; the elu half (all 1.6M threads) is an
// independent DRAM stream whose work fills the permute's idle issue slots.
// ---------------------------------------------------------------------------
__global__ void __launch_bounds__(256) permute_elu_kernel(
    const float* __restrict__ x,     // [N, D]
    const float* __restrict__ w,     // [1, D]
    const int*   __restrict__ src,   // [E]
    const int*   __restrict__ dst)   // [E]
{
    int i = blockIdx.x * blockDim.x + threadIdx.x;

    // ---- permute part: 8 edges per thread ----
    if (i < N_EDGES / 8) {
        int e = i * 8;
        int4 d0 = __ldg(reinterpret_cast<const int4*>(dst + e));
        int4 d1 = __ldg(reinterpret_cast<const int4*>(dst + e) + 1);
        int4 s0 = __ldg(reinterpret_cast<const int4*>(src + e));
        int4 s1 = __ldg(reinterpret_cast<const int4*>(src + e) + 1);

        int p0 = atomicAdd(&g_cursor[d0.x], 1);
        int p1 = atomicAdd(&g_cursor[d0.y], 1);
        int p2 = atomicAdd(&g_cursor[d0.z], 1);
        int p3 = atomicAdd(&g_cursor[d0.w], 1);
        int p4 = atomicAdd(&g_cursor[d1.x], 1);
        int p5 = atomicAdd(&g_cursor[d1.y], 1);
        int p6 = atomicAdd(&g_cursor[d1.z], 1);
        int p7 = atomicAdd(&g_cursor[d1.w], 1);

        g_edge_src[p0] = s0.x;
        g_edge_src[p1] = s0.y;
        g_edge_src[p2] = s0.z;
        g_edge_src[p3] = s0.w;
        g_edge_src[p4] = s1.x;
        g_edge_src[p5] = s1.y;
        g_edge_src[p6] = s1.z;
        g_edge_src[p7] = s1.w;
    }

    // ---- elu part: one float4 -> 4 fp16 per thread ----
    const int total = N_NODES * D / 4;          // 1.6M float4s
    if (i >= total) return;

    float4 xv = __ldg(reinterpret_cast<const float4*>(x) + i);
    float4 wv = __ldg(reinterpret_cast<const float4*>(w) + (i & 15));

    float4 e;
    float p;
    p = xv.x * wv.x; e.x = p > 0.f ? p : (__expf(p) - 1.f);
    p = xv.y * wv.y; e.y = p > 0.f ? p : (__expf(p) - 1.f);
    p = xv.z * wv.z; e.z = p > 0.f ? p : (__expf(p) - 1.f);
    p = xv.w * wv.w; e.w = p > 0.f ? p : (__expf(p) - 1.f);

    __half2 h01 = __floats2half2_rn(e.x, e.y);
    __half2 h23 = __floats2half2_rn(e.z, e.w);
    uint2 st;
    st.x = *reinterpret_cast<unsigned*>(&h01);
    st.y = *reinterpret_cast<unsigned*>(&h23);
    reinterpret_cast<uint2*>(g_emb_h)[i] = st;
}

// ---------------------------------------------------------------------------
// K4: pull-mode gather-sum over fp16 messages, fp32 accumulation.
// 8 threads per node; each owns 8 halfs (16 B). 4-way unrolled. Zero atomics.
// Epilogue re-zeroes g_counts.
// ---------------------------------------------------------------------------
__device__ __forceinline__ void acc_row(float2 a[4], uint4 v)
{
    float2 f;
    f = __half22float2(*reinterpret_cast<__half2*>(&v.x)); a[0].x += f.x; a[0].y += f.y;
    f = __half22float2(*reinterpret_cast<__half2*>(&v.y)); a[1].x += f.x; a[1].y += f.y;
    f = __half22float2(*reinterpret_cast<__half2*>(&v.z)); a[2].x += f.x; a[2].y += f.y;
    f = __half22float2(*reinterpret_cast<__half2*>(&v.w)); a[3].x += f.x; a[3].y += f.y;
}

__global__ void __launch_bounds__(256) gather_kernel(float* __restrict__ out)
{
    int t = blockIdx.x * blockDim.x + threadIdx.x;
    int node = t >> 3;              // 8 threads per node
    int part = t & 7;               // which 8-half chunk of the 64-wide row
    if (node >= N_NODES) return;

    int beg = __ldg(g_offsets + node);
    int end = __ldg(g_offsets + node + 1);

    const uint4* emb16 = reinterpret_cast<const uint4*>(g_emb_h);

    float2 a[4];
    #pragma unroll
    for (int k = 0; k < 4; k++) a[k] = make_float2(0.f, 0.f);

    int j = beg;
    for (; j + 4 <= end; j += 4) {
        int s0 = __ldg(g_edge_src + j);
        int s1 = __ldg(g_edge_src + j + 1);
        int s2 = __ldg(g_edge_src + j + 2);
        int s3 = __ldg(g_edge_src + j + 3);
        uint4 v0 = __ldg(emb16 + s0 * 8 + part);
        uint4 v1 = __ldg(emb16 + s1 * 8 + part);
        uint4 v2 = __ldg(emb16 + s2 * 8 + part);
        uint4 v3 = __ldg(emb16 + s3 * 8 + part);
        acc_row(a, v0);
        acc_row(a, v1);
        acc_row(a, v2);
        acc_row(a, v3);
    }
    for (; j < end; j++) {
        int s0 = __ldg(g_edge_src + j);
        uint4 v0 = __ldg(emb16 + s0 * 8 + part);
        acc_row(a, v0);
    }

    float4* out4 = reinterpret_cast<float4*>(out);
    out4[node * 16 + part * 2 + 0] = make_float4(a[0].x, a[0].y, a[1].x, a[1].y);
    out4[node * 16 + part * 2 + 1] = make_float4(a[2].x, a[2].y, a[3].x, a[3].y);

    if (part == 0) g_counts[node] = 0;   // restore invariant for next call
}

// ---------------------------------------------------------------------------
extern "C" void kernel_launch(void* const* d_in, const int* in_sizes, int n_in,
                              void* d_out, int out_size)
{
    const float* x   = (const float*)d_in[0];   // [100000, 64]
    const float* w   = (const float*)d_in[1];   // [1, 64]
    const int*   src = (const int*)d_in[2];     // [1600000]
    const int*   dst = (const int*)d_in[3];     // [1600000]
    float* out = (float*)d_out;                 // [100000, 64]

    hist_kernel<<<(N_EDGES / 4 + 255) / 256, 256>>>(dst);

    scan_lookback_kernel<<<SCAN_BLOCKS, 256>>>();

    const int total4 = N_NODES * D / 4;         // 1.6M threads
    permute_elu_kernel<<<(total4 + 255) / 256, 256>>>(x, w, src, dst);

    const int gt = N_NODES * 8;                 // 800K threads
    gather_kernel<<<(gt + 255) / 256, 256>>>(out);
}

// round 12
// speedup vs baseline: 1.6612x; 1.0129x over previous
#include <cuda_runtime.h>
#include <cuda_bf16.h>
#include <cuda_fp16.h>

#define N_NODES 100000
#define N_EDGES 1600000
#define D 64

#define N4 (N_NODES / 4)                  // 25000 int4 count words
#define SCAN_BLOCKS ((N4 + 255) / 256)    // 98 (co-resident on 148 SMs)

// ---------------------------------------------------------------------------
// Scratch (no cudaMalloc allowed). __device__ globals zero-init at load;
// g_counts re-zeroed by gather's epilogue, g_status by hist_kernel, so each
// invocation sees a clean state (deterministic).
// ---------------------------------------------------------------------------
__device__ __half g_emb_h[N_NODES * D];            // elu(x*w) in fp16, 12.8 MB
__device__ int    g_counts[N_NODES];               // per-dst degree (0 on entry)
__device__ int    g_offsets[N_NODES + 1];          // CSR row offsets
__device__ int    g_cursor[N_NODES];               // insert cursors
__device__ int    g_edge_src[N_EDGES];             // src ids binned by dst
__device__ unsigned long long g_status[SCAN_BLOCKS]; // lookback: (state<<32)|value

// ---------------------------------------------------------------------------
// K1: dst histogram ONLY (+ zero lookback flags). The elu is deliberately NOT
// here: nothing in the CSR chain needs it, so it moves off the critical path
// into K3. 4 edges per thread via int4; 400K threads.
// ---------------------------------------------------------------------------
__global__ void __launch_bounds__(256) hist_kernel(const int* __restrict__ dst)
{
    int i = blockIdx.x * blockDim.x + threadIdx.x;

    if (i < SCAN_BLOCKS) g_status[i] = 0ULL;

    if (i < N_EDGES / 4) {
        int4 d4 = __ldg(reinterpret_cast<const int4*>(dst) + i);
        atomicAdd(&g_counts[d4.x], 1);
        atomicAdd(&g_counts[d4.y], 1);
        atomicAdd(&g_counts[d4.z], 1);
        atomicAdd(&g_counts[d4.w], 1);
    }
}

// ---------------------------------------------------------------------------
// K2: single-pass decoupled-lookback exclusive scan of g_counts.
// 98 co-resident blocks; states: 0 empty, 1 aggregate, 2 inclusive.
// ---------------------------------------------------------------------------
__global__ void __launch_bounds__(256) scan_lookback_kernel()
{
    __shared__ int warp_sums[8];
    __shared__ int s_base;
    const int b    = blockIdx.x;
    const int tid  = threadIdx.x;
    const int lane = tid & 31;
    const int wid  = tid >> 5;

    int i4 = b * 256 + tid;
    int4 c = make_int4(0, 0, 0, 0);
    if (i4 < N4) c = reinterpret_cast<const int4*>(g_counts)[i4];

    int t0 = c.x;
    int t1 = t0 + c.y;
    int t2 = t1 + c.z;
    int t3 = t2 + c.w;

    int x = t3;
    #pragma unroll
    for (int o = 1; o < 32; o <<= 1) {
        int y = __shfl_up_sync(0xFFFFFFFFu, x, o);
        if (lane >= o) x += y;
    }
    if (lane == 31) warp_sums[wid] = x;
    __syncthreads();

    int warp_excl = 0;
    int block_agg = 0;
    #pragma unroll
    for (int wi = 0; wi < 8; wi++) {
        int ws = warp_sums[wi];
        if (wi < wid) warp_excl += ws;
        block_agg += ws;                 // full block total (all 8 warps)
    }

    int thr_excl = warp_excl + x - t3;

    if (tid == 0) {
        unsigned long long st = (b == 0)
            ? ((2ULL << 32) | (unsigned)block_agg)
            : ((1ULL << 32) | (unsigned)block_agg);
        atomicExch(&g_status[b], st);
    }

    if (wid == 0) {
        int base = 0;
        int idx  = b - 1;
        while (idx >= 0) {
            int my = idx - lane;
            unsigned long long s = 0;
            if (my >= 0) {
                do { s = atomicAdd(&g_status[my], 0ULL); } while ((s >> 32) == 0);
            }
            int st  = (my >= 0) ? (int)(s >> 32) : 1;
            int val = (my >= 0) ? (int)(s & 0xFFFFFFFFu) : 0;

            unsigned incl_mask = __ballot_sync(0xFFFFFFFFu, st == 2);
            int contrib;
            if (incl_mask) {
                int fl = __ffs(incl_mask) - 1;
                contrib = (lane <= fl) ? val : 0;
                #pragma unroll
                for (int o = 16; o; o >>= 1)
                    contrib += __shfl_down_sync(0xFFFFFFFFu, contrib, o);
                base += __shfl_sync(0xFFFFFFFFu, contrib, 0);
                break;
            } else {
                contrib = val;
                #pragma unroll
                for (int o = 16; o; o >>= 1)
                    contrib += __shfl_down_sync(0xFFFFFFFFu, contrib, o);
                base += __shfl_sync(0xFFFFFFFFu, contrib, 0);
                idx -= 32;
            }
        }
        if (lane == 0) {
            s_base = base;
            if (b > 0)
                atomicExch(&g_status[b], (2ULL << 32) | (unsigned)(base + block_agg));
        }
    }
    __syncthreads();

    int base = s_base;
    if (i4 < N4) {
        int e0 = base + thr_excl;
        int4 off = make_int4(e0, e0 + t0, e0 + t1, e0 + t2);
        reinterpret_cast<int4*>(g_offsets)[i4] = off;
        reinterpret_cast<int4*>(g_cursor)[i4]  = off;
    }
    if (b == 0 && tid == 0) g_offsets[N_NODES] = N_EDGES;
}

// ---------------------------------------------------------------------------
// K3: FUSED permute + elu. The permute half (first 200K threads, 8 edges
// each) is atomic-latency bound; the elu half (all 1.6M threads) is an
// independent DRAM stream whose work fills the permute's idle issue slots.
// ---------------------------------------------------------------------------
__global__ void __launch_bounds__(256) permute_elu_kernel(
    const float* __restrict__ x,     // [N, D]
    const float* __restrict__ w,     // [1, D]
    const int*   __restrict__ src,   // [E]
    const int*   __restrict__ dst)   // [E]
{
    int i = blockIdx.x * blockDim.x + threadIdx.x;

    // ---- permute part: 8 edges per thread ----
    if (i < N_EDGES / 8) {
        int e = i * 8;
        int4 d0 = __ldg(reinterpret_cast<const int4*>(dst + e));
        int4 d1 = __ldg(reinterpret_cast<const int4*>(dst + e) + 1);
        int4 s0 = __ldg(reinterpret_cast<const int4*>(src + e));
        int4 s1 = __ldg(reinterpret_cast<const int4*>(src + e) + 1);

        int p0 = atomicAdd(&g_cursor[d0.x], 1);
        int p1 = atomicAdd(&g_cursor[d0.y], 1);
        int p2 = atomicAdd(&g_cursor[d0.z], 1);
        int p3 = atomicAdd(&g_cursor[d0.w], 1);
        int p4 = atomicAdd(&g_cursor[d1.x], 1);
        int p5 = atomicAdd(&g_cursor[d1.y], 1);
        int p6 = atomicAdd(&g_cursor[d1.z], 1);
        int p7 = atomicAdd(&g_cursor[d1.w], 1);

        g_edge_src[p0] = s0.x;
        g_edge_src[p1] = s0.y;
        g_edge_src[p2] = s0.z;
        g_edge_src[p3] = s0.w;
        g_edge_src[p4] = s1.x;
        g_edge_src[p5] = s1.y;
        g_edge_src[p6] = s1.z;
        g_edge_src[p7] = s1.w;
    }

    // ---- elu part: one float4 -> 4 fp16 per thread ----
    const int total = N_NODES * D / 4;          // 1.6M float4s
    if (i >= total) return;

    float4 xv = __ldg(reinterpret_cast<const float4*>(x) + i);
    float4 wv = __ldg(reinterpret_cast<const float4*>(w) + (i & 15));

    float4 e;
    float p;
    p = xv.x * wv.x; e.x = p > 0.f ? p : (__expf(p) - 1.f);
    p = xv.y * wv.y; e.y = p > 0.f ? p : (__expf(p) - 1.f);
    p = xv.z * wv.z; e.z = p > 0.f ? p : (__expf(p) - 1.f);
    p = xv.w * wv.w; e.w = p > 0.f ? p : (__expf(p) - 1.f);

    __half2 h01 = __floats2half2_rn(e.x, e.y);
    __half2 h23 = __floats2half2_rn(e.z, e.w);
    uint2 st;
    st.x = *reinterpret_cast<unsigned*>(&h01);
    st.y = *reinterpret_cast<unsigned*>(&h23);
    reinterpret_cast<uint2*>(g_emb_h)[i] = st;
}

// ---------------------------------------------------------------------------
// K4: pull-mode gather-sum over fp16 messages, fp32 accumulation.
// 8 threads per node; each owns 8 halfs (16 B). 4-way unrolled. Zero atomics.
// Epilogue re-zeroes g_counts.
// ---------------------------------------------------------------------------
__device__ __forceinline__ void acc_row(float2 a[4], uint4 v)
{
    float2 f;
    f = __half22float2(*reinterpret_cast<__half2*>(&v.x)); a[0].x += f.x; a[0].y += f.y;
    f = __half22float2(*reinterpret_cast<__half2*>(&v.y)); a[1].x += f.x; a[1].y += f.y;
    f = __half22float2(*reinterpret_cast<__half2*>(&v.z)); a[2].x += f.x; a[2].y += f.y;
    f = __half22float2(*reinterpret_cast<__half2*>(&v.w)); a[3].x += f.x; a[3].y += f.y;
}

__global__ void __launch_bounds__(256) gather_kernel(float* __restrict__ out)
{
    int t = blockIdx.x * blockDim.x + threadIdx.x;
    int node = t >> 3;              // 8 threads per node
    int part = t & 7;               // which 8-half chunk of the 64-wide row
    if (node >= N_NODES) return;

    int beg = __ldg(g_offsets + node);
    int end = __ldg(g_offsets + node + 1);

    const uint4* emb16 = reinterpret_cast<const uint4*>(g_emb_h);

    float2 a[4];
    #pragma unroll
    for (int k = 0; k < 4; k++) a[k] = make_float2(0.f, 0.f);

    int j = beg;
    for (; j + 4 <= end; j += 4) {
        int s0 = __ldg(g_edge_src + j);
        int s1 = __ldg(g_edge_src + j + 1);
        int s2 = __ldg(g_edge_src + j + 2);
        int s3 = __ldg(g_edge_src + j + 3);
        uint4 v0 = __ldg(emb16 + s0 * 8 + part);
        uint4 v1 = __ldg(emb16 + s1 * 8 + part);
        uint4 v2 = __ldg(emb16 + s2 * 8 + part);
        uint4 v3 = __ldg(emb16 + s3 * 8 + part);
        acc_row(a, v0);
        acc_row(a, v1);
        acc_row(a, v2);
        acc_row(a, v3);
    }
    for (; j < end; j++) {
        int s0 = __ldg(g_edge_src + j);
        uint4 v0 = __ldg(emb16 + s0 * 8 + part);
        acc_row(a, v0);
    }

    float4* out4 = reinterpret_cast<float4*>(out);
    out4[node * 16 + part * 2 + 0] = make_float4(a[0].x, a[0].y, a[1].x, a[1].y);
    out4[node * 16 + part * 2 + 1] = make_float4(a[2].x, a[2].y, a[3].x, a[3].y);

    if (part == 0) g_counts[node] = 0;   // restore invariant for next call
}

// ---------------------------------------------------------------------------
extern "C" void kernel_launch(void* const* d_in, const int* in_sizes, int n_in,
                              void* d_out, int out_size)
{
    const float* x   = (const float*)d_in[0];   // [100000, 64]
    const float* w   = (const float*)d_in[1];   // [1, 64]
    const int*   src = (const int*)d_in[2];     // [1600000]
    const int*   dst = (const int*)d_in[3];     // [1600000]
    float* out = (float*)d_out;                 // [100000, 64]

    hist_kernel<<<(N_EDGES / 4 + 255) / 256, 256>>>(dst);

    scan_lookback_kernel<<<SCAN_BLOCKS, 256>>>();

    const int total4 = N_NODES * D / 4;         // 1.6M threads
    permute_elu_kernel<<<(total4 + 255) / 256, 256>>>(x, w, src, dst);

    const int gt = N_NODES * 8;                 // 800K threads
    gather_kernel<<<(gt + 255) / 256, 256>>>(out);
}